// round 2
// baseline (speedup 1.0000x reference)
#include <cuda_runtime.h>
#include <math.h>

#define NPATH 11
#define DIMF  288
#define BZ    8
#define CHK   64
#define NT    128

__device__ __constant__ int c_l1[NPATH] = {0,1,2,0,1,1,2,0,1,2,2};
__device__ __constant__ int c_l2[NPATH] = {0,1,2,1,0,2,1,2,1,0,2};
__device__ __constant__ int c_lo[NPATH] = {0,0,0,1,1,1,1,2,2,2,2};

__device__ int   g_cnt [NPATH][5];
__device__ int   g_ije [NPATH][5][32];
__device__ float g_vale[NPATH][5][32];

__device__ __forceinline__ double dfact(int n){
  double r = 1.0;
  for (int i = 2; i <= n; ++i) r *= (double)i;
  return r;
}

__device__ double su2_cg_d(int j1,int m1,int j2,int m2,int j3,int m3){
  if (m1 + m2 != m3) return 0.0;
  int vmin = max(max(-j1 + j2 + m3, -j1 + m1), 0);
  int vmax = min(min(j2 + j3 + m1, j3 - j1 + j2), j3 + m3);
  if (vmax < vmin) return 0.0;
  double C = sqrt((2.0*j3 + 1.0)
      * dfact(j3 + j1 - j2) * dfact(j3 - j1 + j2) * dfact(j1 + j2 - j3)
      * dfact(j3 + m3) * dfact(j3 - m3)
      / (dfact(j1 + j2 + j3 + 1) * dfact(j1 - m1) * dfact(j1 + m1)
         * dfact(j2 - m2) * dfact(j2 + m2)));
  double S = 0.0;
  for (int v = vmin; v <= vmax; ++v){
    double t = dfact(j2 + j3 + m1 - v) * dfact(j1 - m1 + v)
             / (dfact(v) * dfact(j3 - j1 + j2 - v) * dfact(j3 + m3 - v)
                * dfact(v + j1 - j2 - m3));
    S += ((v + j2 + m2) & 1) ? -t : t;
  }
  return C * S;
}

// entry (a,b) of e3nn real->complex basis q for angular momentum l, incl (-i)^l
__device__ __forceinline__ void q_entry(int l, int a, int b, double& re, double& im){
  double r = 0.0, i = 0.0;
  int m = a - l;
  const double s2 = 0.70710678118654752440;
  if (m < 0){
    if (b == l - m) r =  s2;
    if (b == l + m) i = -s2;
  } else if (m == 0){
    if (b == l) r = 1.0;
  } else {
    double s = (m & 1) ? -1.0 : 1.0;
    if (b == l + m) r = s * s2;
    if (b == l - m) i = s * s2;
  }
  if (l == 1){ double t = r; r = i; i = -t; }   // *(-i)
  else if (l == 2){ r = -r; i = -i; }           // *(-1)
  re = r; im = i;
}

__global__ void w3j_init(){
  int p  = blockIdx.x;
  int l1 = c_l1[p], l2 = c_l2[p], l3 = c_lo[p];
  int d1 = 2*l1+1, d2 = 2*l2+1, d3 = 2*l3+1;
  int tid = threadIdx.x;
  __shared__ double cg[125];
  __shared__ double Cv[125];
  __shared__ double s_inorm;
  int E = d1*d2*d3;
  for (int e = tid; e < E; e += blockDim.x) cg[e] = 0.0;
  __syncthreads();
  for (int e = tid; e < d1*d2; e += blockDim.x){
    int i = e / d2, k = e % d2;
    int m1 = i - l1, m2 = k - l2;
    if (abs(m1 + m2) <= l3)
      cg[(i*d2 + k)*d3 + (l3 + m1 + m2)] = su2_cg_d(l1, m1, l2, m2, l3, m1 + m2);
  }
  __syncthreads();
  // C[j,l,m] = sum_{i,k,n} q1[i,j] q2[k,l] conj(q3[n,m]) cg[i,k,n]
  for (int e = tid; e < E; e += blockDim.x){
    int jj = e/(d2*d3), rem = e%(d2*d3), ll = rem/d3, mm = rem%d3;
    double cr = 0.0;
    for (int i = 0; i < d1; ++i){
      double q1r,q1i; q_entry(l1,i,jj,q1r,q1i);
      if (q1r==0.0 && q1i==0.0) continue;
      for (int k = 0; k < d2; ++k){
        double q2r,q2i; q_entry(l2,k,ll,q2r,q2i);
        if (q2r==0.0 && q2i==0.0) continue;
        int n = (i-l1)+(k-l2)+l3;
        if (n < 0 || n >= d3) continue;
        double g = cg[(i*d2+k)*d3 + n];
        if (g == 0.0) continue;
        double q3r,q3i; q_entry(l3,n,mm,q3r,q3i);
        q3i = -q3i;
        double ar = q1r*q2r - q1i*q2i;
        double ai = q1r*q2i + q1i*q2r;
        cr += g * (ar*q3r - ai*q3i);
      }
    }
    Cv[e] = cr;
  }
  __syncthreads();
  if (tid == 0){
    double s = 0.0;
    for (int e = 0; e < E; ++e) s += Cv[e]*Cv[e];
    s_inorm = 1.0/sqrt(s);
  }
  __syncthreads();
  if (tid < d3){
    int mm = tid, cnt = 0;
    for (int i = 0; i < d1; ++i)
      for (int j = 0; j < d2; ++j){
        double v = Cv[(i*d2+j)*d3 + mm] * s_inorm;
        if (fabs(v) > 1e-9){
          g_ije [p][mm][cnt] = i | (j << 8);
          g_vale[p][mm][cnt] = (float)v;
          ++cnt;
        }
      }
    g_cnt[p][mm] = cnt;
  }
}

// ------------------------- main kernel -------------------------------------
template<int L1, int L2, int LO>
__device__ __forceinline__ void process_path(
    int p, const float* __restrict__ ws,
    const float* x1s, const float* x2s,
    float* wss, float* Ts, int* s_cnt, int* s_ij, float* s_val,
    float* acc0, float* acc1, int tid, int wt, int zs)
{
  constexpr int D1 = 2*L1+1, D2 = 2*L2+1, K = 2*LO+1;
  constexpr int O1 = (L1==0)?0:((L1==1)?32:128);
  constexpr int O2 = (L2==0)?0:((L2==1)?32:128);
  constexpr int AO = (LO==0)?0:((LO==1)?1:4);

  __syncthreads();
  if (tid < K) s_cnt[tid] = g_cnt[p][tid];
  for (int e = tid; e < K*32; e += NT){
    s_ij [e] = g_ije [p][e>>5][e&31];
    s_val[e] = g_vale[p][e>>5][e&31];
  }
  const float* wsp = ws + (size_t)p * 32768;

  for (int ch = 0; ch < 1024/CHK; ++ch){
    __syncthreads();
    for (int e = tid; e < CHK*32; e += NT)
      wss[e] = __ldg(wsp + ch*CHK*32 + e);
    for (int e = tid; e < CHK*BZ; e += NT){
      int z = e & (BZ-1);
      int c = e / BZ;
      int uv = ch*CHK + c;
      const float* a1 = x1s + z*(DIMF+1) + O1 + (uv>>5)*D1;
      const float* a2 = x2s + z*(DIMF+1) + O2 + (uv&31)*D2;
      #pragma unroll
      for (int k = 0; k < K; ++k){
        float t = 0.f;
        int cnt = s_cnt[k];
        for (int q = 0; q < cnt; ++q){
          int ij = s_ij[(k<<5)+q];
          t += s_val[(k<<5)+q] * a1[ij & 255] * a2[ij >> 8];
        }
        Ts[(c*K + k)*BZ + z] = t;
      }
    }
    __syncthreads();
    #pragma unroll 4
    for (int c = 0; c < CHK; ++c){
      float w0 = wss[(c<<5) + wt];
      float w1 = wss[(c<<5) + wt + 16];
      #pragma unroll
      for (int k = 0; k < K; ++k){
        float t = Ts[(c*K + k)*BZ + zs];
        acc0[AO+k] = fmaf(w0, t, acc0[AO+k]);
        acc1[AO+k] = fmaf(w1, t, acc1[AO+k]);
      }
    }
  }
}

__global__ void __launch_bounds__(NT, 4) tp_kernel(
    const float* __restrict__ x1, const float* __restrict__ x2,
    const float* __restrict__ ws, float* __restrict__ out)
{
  __shared__ float x1s[BZ*(DIMF+1)];
  __shared__ float x2s[BZ*(DIMF+1)];
  __shared__ float wss[CHK*32];
  __shared__ float Ts [CHK*5*BZ];
  __shared__ float s_val[5*32];
  __shared__ int   s_ij [5*32];
  __shared__ int   s_cnt[5];

  int tid = threadIdx.x;
  int wt  = tid & 15;      // owns w = wt and wt+16
  int zs  = tid >> 4;      // 0..7
  int zbase = blockIdx.x * BZ;

  for (int e = tid; e < BZ*DIMF; e += NT){
    int z = e / DIMF, c = e - z*DIMF;
    x1s[z*(DIMF+1)+c] = x1[(size_t)(zbase+z)*DIMF + c];
    x2s[z*(DIMF+1)+c] = x2[(size_t)(zbase+z)*DIMF + c];
  }

  float acc0[9], acc1[9];
  #pragma unroll
  for (int i = 0; i < 9; ++i){ acc0[i]=0.f; acc1[i]=0.f; }

  process_path<0,0,0>( 0, ws, x1s,x2s, wss,Ts,s_cnt,s_ij,s_val, acc0,acc1, tid,wt,zs);
  process_path<1,1,0>( 1, ws, x1s,x2s, wss,Ts,s_cnt,s_ij,s_val, acc0,acc1, tid,wt,zs);
  process_path<2,2,0>( 2, ws, x1s,x2s, wss,Ts,s_cnt,s_ij,s_val, acc0,acc1, tid,wt,zs);
  process_path<0,1,1>( 3, ws, x1s,x2s, wss,Ts,s_cnt,s_ij,s_val, acc0,acc1, tid,wt,zs);
  process_path<1,0,1>( 4, ws, x1s,x2s, wss,Ts,s_cnt,s_ij,s_val, acc0,acc1, tid,wt,zs);
  process_path<1,2,1>( 5, ws, x1s,x2s, wss,Ts,s_cnt,s_ij,s_val, acc0,acc1, tid,wt,zs);
  process_path<2,1,1>( 6, ws, x1s,x2s, wss,Ts,s_cnt,s_ij,s_val, acc0,acc1, tid,wt,zs);
  process_path<0,2,2>( 7, ws, x1s,x2s, wss,Ts,s_cnt,s_ij,s_val, acc0,acc1, tid,wt,zs);
  process_path<1,1,2>( 8, ws, x1s,x2s, wss,Ts,s_cnt,s_ij,s_val, acc0,acc1, tid,wt,zs);
  process_path<2,0,2>( 9, ws, x1s,x2s, wss,Ts,s_cnt,s_ij,s_val, acc0,acc1, tid,wt,zs);
  process_path<2,2,2>(10, ws, x1s,x2s, wss,Ts,s_cnt,s_ij,s_val, acc0,acc1, tid,wt,zs);

  const float A0 = 0.01804219591217583f;   // sqrt(1/3072)
  const float A1 = 0.02706329386826371f;   // sqrt(3)/64
  const float A2 = 0.03493856214843422f;   // sqrt(5)/64

  float* o = out + (size_t)(zbase + zs) * DIMF;
  int w0 = wt, w1 = wt + 16;
  o[w0] = A0 * acc0[0];
  o[w1] = A0 * acc1[0];
  #pragma unroll
  for (int k = 0; k < 3; ++k){
    o[32 + w0*3 + k] = A1 * acc0[1+k];
    o[32 + w1*3 + k] = A1 * acc1[1+k];
  }
  #pragma unroll
  for (int k = 0; k < 5; ++k){
    o[128 + w0*5 + k] = A2 * acc0[4+k];
    o[128 + w1*5 + k] = A2 * acc1[4+k];
  }
}

extern "C" void kernel_launch(void* const* d_in, const int* in_sizes, int n_in,
                              void* d_out, int out_size) {
  const float* x1 = (const float*)d_in[0];
  const float* x2 = (const float*)d_in[1];
  const float* ws = (const float*)d_in[2];
  float* out = (float*)d_out;
  (void)in_sizes; (void)n_in; (void)out_size;
  w3j_init<<<NPATH, 64>>>();
  tp_kernel<<<2048/BZ, NT>>>(x1, x2, ws, out);
}

// round 3
// speedup vs baseline: 1.0840x; 1.0840x over previous
#include <cuda_runtime.h>
#include <math.h>

#define NPATH 11
#define DIMF  288
#define BZ    8
#define CHK   64
#define NT    128
#define UVS   4            // uv-split factor
#define CHPC  (16/UVS)     // chunks per CTA per path
#define WPAD  68           // padded stride for transposed weights

__device__ __constant__ int c_l1[NPATH] = {0,1,2,0,1,1,2,0,1,2,2};
__device__ __constant__ int c_l2[NPATH] = {0,1,2,1,0,2,1,2,1,0,2};
__device__ __constant__ int c_lo[NPATH] = {0,0,0,1,1,1,1,2,2,2,2};

__device__ int   g_cnt [NPATH][5];
__device__ int   g_ije [NPATH][5][32];
__device__ float g_vale[NPATH][5][32];
__device__ float g_part[UVS][2048*DIMF];   // 9.4 MB scratch partials

__device__ __forceinline__ double dfact(int n){
  double r = 1.0;
  for (int i = 2; i <= n; ++i) r *= (double)i;
  return r;
}

__device__ double su2_cg_d(int j1,int m1,int j2,int m2,int j3,int m3){
  if (m1 + m2 != m3) return 0.0;
  int vmin = max(max(-j1 + j2 + m3, -j1 + m1), 0);
  int vmax = min(min(j2 + j3 + m1, j3 - j1 + j2), j3 + m3);
  if (vmax < vmin) return 0.0;
  double C = sqrt((2.0*j3 + 1.0)
      * dfact(j3 + j1 - j2) * dfact(j3 - j1 + j2) * dfact(j1 + j2 - j3)
      * dfact(j3 + m3) * dfact(j3 - m3)
      / (dfact(j1 + j2 + j3 + 1) * dfact(j1 - m1) * dfact(j1 + m1)
         * dfact(j2 - m2) * dfact(j2 + m2)));
  double S = 0.0;
  for (int v = vmin; v <= vmax; ++v){
    double t = dfact(j2 + j3 + m1 - v) * dfact(j1 - m1 + v)
             / (dfact(v) * dfact(j3 - j1 + j2 - v) * dfact(j3 + m3 - v)
                * dfact(v + j1 - j2 - m3));
    S += ((v + j2 + m2) & 1) ? -t : t;
  }
  return C * S;
}

__device__ __forceinline__ void q_entry(int l, int a, int b, double& re, double& im){
  double r = 0.0, i = 0.0;
  int m = a - l;
  const double s2 = 0.70710678118654752440;
  if (m < 0){
    if (b == l - m) r =  s2;
    if (b == l + m) i = -s2;
  } else if (m == 0){
    if (b == l) r = 1.0;
  } else {
    double s = (m & 1) ? -1.0 : 1.0;
    if (b == l + m) r = s * s2;
    if (b == l - m) i = s * s2;
  }
  if (l == 1){ double t = r; r = i; i = -t; }   // *(-i)
  else if (l == 2){ r = -r; i = -i; }           // *(-1)
  re = r; im = i;
}

__global__ void w3j_init(){
  int p  = blockIdx.x;
  int l1 = c_l1[p], l2 = c_l2[p], l3 = c_lo[p];
  int d1 = 2*l1+1, d2 = 2*l2+1, d3 = 2*l3+1;
  int tid = threadIdx.x;
  __shared__ double cg[125];
  __shared__ double Cv[125];
  __shared__ double s_inorm;
  int E = d1*d2*d3;
  for (int e = tid; e < E; e += blockDim.x) cg[e] = 0.0;
  __syncthreads();
  for (int e = tid; e < d1*d2; e += blockDim.x){
    int i = e / d2, k = e % d2;
    int m1 = i - l1, m2 = k - l2;
    if (abs(m1 + m2) <= l3)
      cg[(i*d2 + k)*d3 + (l3 + m1 + m2)] = su2_cg_d(l1, m1, l2, m2, l3, m1 + m2);
  }
  __syncthreads();
  for (int e = tid; e < E; e += blockDim.x){
    int jj = e/(d2*d3), rem = e%(d2*d3), ll = rem/d3, mm = rem%d3;
    double cr = 0.0;
    for (int i = 0; i < d1; ++i){
      double q1r,q1i; q_entry(l1,i,jj,q1r,q1i);
      if (q1r==0.0 && q1i==0.0) continue;
      for (int k = 0; k < d2; ++k){
        double q2r,q2i; q_entry(l2,k,ll,q2r,q2i);
        if (q2r==0.0 && q2i==0.0) continue;
        int n = (i-l1)+(k-l2)+l3;
        if (n < 0 || n >= d3) continue;
        double g = cg[(i*d2+k)*d3 + n];
        if (g == 0.0) continue;
        double q3r,q3i; q_entry(l3,n,mm,q3r,q3i);
        q3i = -q3i;
        double ar = q1r*q2r - q1i*q2i;
        double ai = q1r*q2i + q1i*q2r;
        cr += g * (ar*q3r - ai*q3i);
      }
    }
    Cv[e] = cr;
  }
  __syncthreads();
  if (tid == 0){
    double s = 0.0;
    for (int e = 0; e < E; ++e) s += Cv[e]*Cv[e];
    s_inorm = 1.0/sqrt(s);
  }
  __syncthreads();
  if (tid < d3){
    int mm = tid, cnt = 0;
    for (int i = 0; i < d1; ++i)
      for (int j = 0; j < d2; ++j){
        double v = Cv[(i*d2+j)*d3 + mm] * s_inorm;
        if (fabs(v) > 1e-9){
          g_ije [p][mm][cnt] = i | (j << 8);
          g_vale[p][mm][cnt] = (float)v;
          ++cnt;
        }
      }
    g_cnt[p][mm] = cnt;
  }
}

// ------------------------- main kernel -------------------------------------
template<int L1, int L2, int LO>
__device__ __forceinline__ void process_path(
    int p, int ch0, const float* __restrict__ ws,
    const float* x1s, const float* x2s,
    float* wss, float* Ts, int* s_cnt, int* s_ij, float* s_val,
    float* acc0, float* acc1, int tid, int wt, int zs)
{
  constexpr int D1 = 2*L1+1, D2 = 2*L2+1, K = 2*LO+1;
  constexpr int O1 = (L1==0)?0:((L1==1)?32:128);
  constexpr int O2 = (L2==0)?0:((L2==1)?32:128);
  constexpr int AO = (LO==0)?0:((LO==1)?1:4);

  __syncthreads();
  if (tid < K) s_cnt[tid] = g_cnt[p][tid];
  for (int e = tid; e < K*32; e += NT){
    s_ij [e] = g_ije [p][e>>5][e&31];
    s_val[e] = g_vale[p][e>>5][e&31];
  }
  const float* wsp = ws + (size_t)p * 32768;

  for (int ch = ch0; ch < ch0 + CHPC; ++ch){
    __syncthreads();
    // stage weights TRANSPOSED: wss[w*WPAD + c] = ws[p][ch*64+c][w]
    for (int e = tid; e < CHK*32; e += NT){
      int c = e >> 5, w = e & 31;
      wss[w*WPAD + c] = __ldg(wsp + ch*CHK*32 + e);
    }
    // build T[z][k][c]
    for (int e = tid; e < CHK*BZ; e += NT){
      int c = e & (CHK-1);
      int z = e >> 6;
      int uv = ch*CHK + c;
      const float* a1 = x1s + z*(DIMF+1) + O1 + (uv>>5)*D1;
      const float* a2 = x2s + z*(DIMF+1) + O2 + (uv&31)*D2;
      #pragma unroll
      for (int k = 0; k < K; ++k){
        float t = 0.f;
        int cnt = s_cnt[k];
        for (int q = 0; q < cnt; ++q){
          int ij = s_ij[(k<<5)+q];
          t += s_val[(k<<5)+q] * a1[ij & 255] * a2[ij >> 8];
        }
        Ts[(z*K + k)*CHK + c] = t;
      }
    }
    __syncthreads();
    // vectorized rank-1 sweep: float4 over c
    const float4* wv0 = (const float4*)(wss + wt*WPAD);
    const float4* wv1 = (const float4*)(wss + (wt+16)*WPAD);
    #pragma unroll 4
    for (int c4 = 0; c4 < CHK/4; ++c4){
      float4 wa = wv0[c4];
      float4 wb = wv1[c4];
      #pragma unroll
      for (int k = 0; k < K; ++k){
        float4 t = ((const float4*)(Ts + (zs*K + k)*CHK))[c4];
        acc0[AO+k] = fmaf(wa.x, t.x, fmaf(wa.y, t.y, fmaf(wa.z, t.z, fmaf(wa.w, t.w, acc0[AO+k]))));
        acc1[AO+k] = fmaf(wb.x, t.x, fmaf(wb.y, t.y, fmaf(wb.z, t.z, fmaf(wb.w, t.w, acc1[AO+k]))));
      }
    }
  }
}

__global__ void __launch_bounds__(NT, 4) tp_kernel(
    const float* __restrict__ x1, const float* __restrict__ x2,
    const float* __restrict__ ws)
{
  __shared__ float x1s[BZ*(DIMF+1)];
  __shared__ float x2s[BZ*(DIMF+1)];
  __shared__ float wss[32*WPAD];
  __shared__ float Ts [BZ*5*CHK];
  __shared__ float s_val[5*32];
  __shared__ int   s_ij [5*32];
  __shared__ int   s_cnt[5];

  int tid  = threadIdx.x;
  int wt   = tid & 15;
  int zs   = tid >> 4;
  int bid  = blockIdx.x;
  int half = bid & (UVS-1);
  int ch0  = half * CHPC;
  int zbase = (bid >> 2) * BZ;

  for (int e = tid; e < BZ*DIMF; e += NT){
    int z = e / DIMF, c = e - z*DIMF;
    x1s[z*(DIMF+1)+c] = x1[(size_t)(zbase+z)*DIMF + c];
    x2s[z*(DIMF+1)+c] = x2[(size_t)(zbase+z)*DIMF + c];
  }

  float acc0[9], acc1[9];
  #pragma unroll
  for (int i = 0; i < 9; ++i){ acc0[i]=0.f; acc1[i]=0.f; }

  process_path<0,0,0>( 0, ch0, ws, x1s,x2s, wss,Ts,s_cnt,s_ij,s_val, acc0,acc1, tid,wt,zs);
  process_path<1,1,0>( 1, ch0, ws, x1s,x2s, wss,Ts,s_cnt,s_ij,s_val, acc0,acc1, tid,wt,zs);
  process_path<2,2,0>( 2, ch0, ws, x1s,x2s, wss,Ts,s_cnt,s_ij,s_val, acc0,acc1, tid,wt,zs);
  process_path<0,1,1>( 3, ch0, ws, x1s,x2s, wss,Ts,s_cnt,s_ij,s_val, acc0,acc1, tid,wt,zs);
  process_path<1,0,1>( 4, ch0, ws, x1s,x2s, wss,Ts,s_cnt,s_ij,s_val, acc0,acc1, tid,wt,zs);
  process_path<1,2,1>( 5, ch0, ws, x1s,x2s, wss,Ts,s_cnt,s_ij,s_val, acc0,acc1, tid,wt,zs);
  process_path<2,1,1>( 6, ch0, ws, x1s,x2s, wss,Ts,s_cnt,s_ij,s_val, acc0,acc1, tid,wt,zs);
  process_path<0,2,2>( 7, ch0, ws, x1s,x2s, wss,Ts,s_cnt,s_ij,s_val, acc0,acc1, tid,wt,zs);
  process_path<1,1,2>( 8, ch0, ws, x1s,x2s, wss,Ts,s_cnt,s_ij,s_val, acc0,acc1, tid,wt,zs);
  process_path<2,0,2>( 9, ch0, ws, x1s,x2s, wss,Ts,s_cnt,s_ij,s_val, acc0,acc1, tid,wt,zs);
  process_path<2,2,2>(10, ch0, ws, x1s,x2s, wss,Ts,s_cnt,s_ij,s_val, acc0,acc1, tid,wt,zs);

  const float A0 = 0.01804219591217583f;   // sqrt(1/3072)
  const float A1 = 0.02706329386826371f;   // sqrt(3)/64
  const float A2 = 0.03493856214843422f;   // sqrt(5)/64

  float* o = g_part[half] + (size_t)(zbase + zs) * DIMF;
  int w0 = wt, w1 = wt + 16;
  o[w0] = A0 * acc0[0];
  o[w1] = A0 * acc1[0];
  #pragma unroll
  for (int k = 0; k < 3; ++k){
    o[32 + w0*3 + k] = A1 * acc0[1+k];
    o[32 + w1*3 + k] = A1 * acc1[1+k];
  }
  #pragma unroll
  for (int k = 0; k < 5; ++k){
    o[128 + w0*5 + k] = A2 * acc0[4+k];
    o[128 + w1*5 + k] = A2 * acc1[4+k];
  }
}

__global__ void reduce_kernel(float* __restrict__ out){
  int i = blockIdx.x * blockDim.x + threadIdx.x;   // float4 index, 147456 total
  float4 a = ((const float4*)g_part[0])[i];
  float4 b = ((const float4*)g_part[1])[i];
  float4 c = ((const float4*)g_part[2])[i];
  float4 d = ((const float4*)g_part[3])[i];
  float4 r;
  r.x = (a.x + b.x) + (c.x + d.x);
  r.y = (a.y + b.y) + (c.y + d.y);
  r.z = (a.z + b.z) + (c.z + d.z);
  r.w = (a.w + b.w) + (c.w + d.w);
  ((float4*)out)[i] = r;
}

extern "C" void kernel_launch(void* const* d_in, const int* in_sizes, int n_in,
                              void* d_out, int out_size) {
  const float* x1 = (const float*)d_in[0];
  const float* x2 = (const float*)d_in[1];
  const float* ws = (const float*)d_in[2];
  float* out = (float*)d_out;
  (void)in_sizes; (void)n_in; (void)out_size;
  w3j_init<<<NPATH, 64>>>();
  tp_kernel<<<(2048/BZ)*UVS, NT>>>(x1, x2, ws);
  reduce_kernel<<<(2048*DIMF/4)/256, 256>>>(out);
}

// round 4
// speedup vs baseline: 1.4115x; 1.3020x over previous
#include <cuda_runtime.h>
#include <math.h>

#define NPATH 11
#define DIMF  288
#define BZ    8
#define CHK   64
#define NT    128
#define UVS   4            // uv-split factor
#define CHPC  (16/UVS)     // chunks per CTA per path
#define WPAD  68           // padded stride for transposed weights

__device__ __constant__ int c_l1[NPATH] = {0,1,2,0,1,1,2,0,1,2,2};
__device__ __constant__ int c_l2[NPATH] = {0,1,2,1,0,2,1,2,1,0,2};
__device__ __constant__ int c_lo[NPATH] = {0,0,0,1,1,1,1,2,2,2,2};

__device__ int   g_cnt [NPATH][5];
__device__ int   g_ije [NPATH][5][32];
__device__ float g_vale[NPATH][5][32];
__device__ float g_part[UVS][2048*DIMF];   // 9.4 MB scratch partials

__device__ double su2_cg_t(const double* f, int j1,int m1,int j2,int m2,int j3,int m3){
  if (m1 + m2 != m3) return 0.0;
  int vmin = max(max(-j1 + j2 + m3, -j1 + m1), 0);
  int vmax = min(min(j2 + j3 + m1, j3 - j1 + j2), j3 + m3);
  if (vmax < vmin) return 0.0;
  double C = sqrt((2.0*j3 + 1.0)
      * f[j3 + j1 - j2] * f[j3 - j1 + j2] * f[j1 + j2 - j3]
      * f[j3 + m3] * f[j3 - m3]
      / (f[j1 + j2 + j3 + 1] * f[j1 - m1] * f[j1 + m1]
         * f[j2 - m2] * f[j2 + m2]));
  double S = 0.0;
  for (int v = vmin; v <= vmax; ++v){
    double t = f[j2 + j3 + m1 - v] * f[j1 - m1 + v]
             / (f[v] * f[j3 - j1 + j2 - v] * f[j3 + m3 - v]
                * f[v + j1 - j2 - m3]);
    S += ((v + j2 + m2) & 1) ? -t : t;
  }
  return C * S;
}

__device__ __forceinline__ void q_entry(int l, int a, int b, double& re, double& im){
  double r = 0.0, i = 0.0;
  int m = a - l;
  const double s2 = 0.70710678118654752440;
  if (m < 0){
    if (b == l - m) r =  s2;
    if (b == l + m) i = -s2;
  } else if (m == 0){
    if (b == l) r = 1.0;
  } else {
    double s = (m & 1) ? -1.0 : 1.0;
    if (b == l + m) r = s * s2;
    if (b == l - m) i = s * s2;
  }
  if (l == 1){ double t = r; r = i; i = -t; }   // *(-i)
  else if (l == 2){ r = -r; i = -i; }           // *(-1)
  re = r; im = i;
}

__global__ void w3j_init(){
  int p  = blockIdx.x;
  int l1 = c_l1[p], l2 = c_l2[p], l3 = c_lo[p];
  int d1 = 2*l1+1, d2 = 2*l2+1, d3 = 2*l3+1;
  int tid = threadIdx.x;
  __shared__ double sf[16];
  __shared__ double cg[125];
  __shared__ double Cv[125];
  __shared__ double ps[128];
  __shared__ double s_inorm;

  if (tid == 0){
    double r = 1.0;
    sf[0] = 1.0;
    for (int i = 1; i < 16; ++i){ r *= (double)i; sf[i] = r; }
  }
  int E = d1*d2*d3;
  for (int e = tid; e < E; e += blockDim.x) cg[e] = 0.0;
  // zero + pad coefficient tables
  if (tid < d3) {
    for (int q = 0; q < 32; ++q){ g_ije[p][tid][q] = 0; g_vale[p][tid][q] = 0.f; }
  }
  __syncthreads();
  for (int e = tid; e < d1*d2; e += blockDim.x){
    int i = e / d2, k = e % d2;
    int m1 = i - l1, m2 = k - l2;
    if (abs(m1 + m2) <= l3)
      cg[(i*d2 + k)*d3 + (l3 + m1 + m2)] = su2_cg_t(sf, l1, m1, l2, m2, l3, m1 + m2);
  }
  __syncthreads();
  for (int e = tid; e < E; e += blockDim.x){
    int jj = e/(d2*d3), rem = e%(d2*d3), ll = rem/d3, mm = rem%d3;
    double cr = 0.0;
    for (int i = 0; i < d1; ++i){
      double q1r,q1i; q_entry(l1,i,jj,q1r,q1i);
      if (q1r==0.0 && q1i==0.0) continue;
      for (int k = 0; k < d2; ++k){
        double q2r,q2i; q_entry(l2,k,ll,q2r,q2i);
        if (q2r==0.0 && q2i==0.0) continue;
        int n = (i-l1)+(k-l2)+l3;
        if (n < 0 || n >= d3) continue;
        double g = cg[(i*d2+k)*d3 + n];
        if (g == 0.0) continue;
        double q3r,q3i; q_entry(l3,n,mm,q3r,q3i);
        q3i = -q3i;
        double ar = q1r*q2r - q1i*q2i;
        double ai = q1r*q2i + q1i*q2r;
        cr += g * (ar*q3r - ai*q3i);
      }
    }
    Cv[e] = cr;
  }
  __syncthreads();
  {
    double acc = 0.0;
    for (int e = tid; e < E; e += blockDim.x) acc += Cv[e]*Cv[e];
    ps[tid] = acc;
  }
  __syncthreads();
  if (tid == 0){
    double s0=0,s1=0,s2=0,s3=0;
    for (int i = 0; i < 128; i += 4){ s0+=ps[i]; s1+=ps[i+1]; s2+=ps[i+2]; s3+=ps[i+3]; }
    s_inorm = 1.0/sqrt((s0+s1)+(s2+s3));
  }
  __syncthreads();
  if (tid < d3){
    int mm = tid, cnt = 0;
    for (int i = 0; i < d1; ++i)
      for (int j = 0; j < d2; ++j){
        double v = Cv[(i*d2+j)*d3 + mm] * s_inorm;
        if (fabs(v) > 1e-9){
          g_ije [p][mm][cnt] = i | (j << 8);
          g_vale[p][mm][cnt] = (float)v;
          ++cnt;
        }
      }
    g_cnt[p][mm] = (cnt + 3) & ~3;   // padded entries are zero
  }
}

// ------------------------- main kernel -------------------------------------
template<int L1, int L2, int LO>
__device__ __forceinline__ void process_path(
    int p, int ch0, const float* __restrict__ ws,
    const float* x1s, const float* x2s,
    float* wss, float* Ts, int* s_cnt, int* s_ij, float* s_val,
    float* acc0, float* acc1, int tid, int wt, int zs)
{
  constexpr int D1 = 2*L1+1, D2 = 2*L2+1, K = 2*LO+1;
  constexpr int O1 = (L1==0)?0:((L1==1)?32:128);
  constexpr int O2 = (L2==0)?0:((L2==1)?32:128);
  constexpr int AO = (LO==0)?0:((LO==1)?1:4);

  __syncthreads();
  if (tid < K) s_cnt[tid] = g_cnt[p][tid];
  for (int e = tid; e < K*32; e += NT){
    s_ij [e] = g_ije [p][e>>5][e&31];
    s_val[e] = g_vale[p][e>>5][e&31];
  }
  const float* wsp = ws + (size_t)p * 32768;

  for (int ch = ch0; ch < ch0 + CHPC; ++ch){
    __syncthreads();
    // stage weights TRANSPOSED: wss[w*WPAD + c]
    for (int e = tid; e < CHK*32; e += NT){
      int c = e >> 5, w = e & 31;
      wss[w*WPAD + c] = __ldg(wsp + ch*CHK*32 + e);
    }
    // build T[z][k][c] with 4-way independent partials
    for (int e = tid; e < CHK*BZ; e += NT){
      int c = e & (CHK-1);
      int z = e >> 6;
      int uv = ch*CHK + c;
      const float* a1 = x1s + z*(DIMF+1) + O1 + (uv>>5)*D1;
      const float* a2 = x2s + z*(DIMF+1) + O2 + (uv&31)*D2;
      #pragma unroll
      for (int k = 0; k < K; ++k){
        int cnt = s_cnt[k];
        const int*   ij = s_ij  + (k<<5);
        const float* vl = s_val + (k<<5);
        float t0=0.f, t1=0.f, t2=0.f, t3=0.f;
        for (int q = 0; q < cnt; q += 4){
          int i0 = ij[q], i1 = ij[q+1], i2 = ij[q+2], i3 = ij[q+3];
          t0 = fmaf(vl[q  ], a1[i0 & 255] * a2[i0 >> 8], t0);
          t1 = fmaf(vl[q+1], a1[i1 & 255] * a2[i1 >> 8], t1);
          t2 = fmaf(vl[q+2], a1[i2 & 255] * a2[i2 >> 8], t2);
          t3 = fmaf(vl[q+3], a1[i3 & 255] * a2[i3 >> 8], t3);
        }
        Ts[(z*K + k)*CHK + c] = (t0 + t1) + (t2 + t3);
      }
    }
    __syncthreads();
    // vectorized rank-1 sweep: float4 over c
    const float4* wv0 = (const float4*)(wss + wt*WPAD);
    const float4* wv1 = (const float4*)(wss + (wt+16)*WPAD);
    #pragma unroll 4
    for (int c4 = 0; c4 < CHK/4; ++c4){
      float4 wa = wv0[c4];
      float4 wb = wv1[c4];
      #pragma unroll
      for (int k = 0; k < K; ++k){
        float4 t = ((const float4*)(Ts + (zs*K + k)*CHK))[c4];
        acc0[AO+k] = fmaf(wa.x, t.x, fmaf(wa.y, t.y, fmaf(wa.z, t.z, fmaf(wa.w, t.w, acc0[AO+k]))));
        acc1[AO+k] = fmaf(wb.x, t.x, fmaf(wb.y, t.y, fmaf(wb.z, t.z, fmaf(wb.w, t.w, acc1[AO+k]))));
      }
    }
  }
}

__global__ void __launch_bounds__(NT, 5) tp_kernel(
    const float* __restrict__ x1, const float* __restrict__ x2,
    const float* __restrict__ ws)
{
  __shared__ float x1s[BZ*(DIMF+1)];
  __shared__ float x2s[BZ*(DIMF+1)];
  __shared__ float wss[32*WPAD];
  __shared__ float Ts [BZ*5*CHK];
  __shared__ float s_val[5*32];
  __shared__ int   s_ij [5*32];
  __shared__ int   s_cnt[5];

  int tid  = threadIdx.x;
  int wt   = tid & 15;
  int zs   = tid >> 4;
  int bid  = blockIdx.x;
  int half = bid & (UVS-1);
  int ch0  = half * CHPC;
  int zbase = (bid >> 2) * BZ;

  for (int e = tid; e < BZ*DIMF; e += NT){
    int z = e / DIMF, c = e - z*DIMF;
    x1s[z*(DIMF+1)+c] = x1[(size_t)(zbase+z)*DIMF + c];
    x2s[z*(DIMF+1)+c] = x2[(size_t)(zbase+z)*DIMF + c];
  }

  float acc0[9], acc1[9];
  #pragma unroll
  for (int i = 0; i < 9; ++i){ acc0[i]=0.f; acc1[i]=0.f; }

  process_path<0,0,0>( 0, ch0, ws, x1s,x2s, wss,Ts,s_cnt,s_ij,s_val, acc0,acc1, tid,wt,zs);
  process_path<1,1,0>( 1, ch0, ws, x1s,x2s, wss,Ts,s_cnt,s_ij,s_val, acc0,acc1, tid,wt,zs);
  process_path<2,2,0>( 2, ch0, ws, x1s,x2s, wss,Ts,s_cnt,s_ij,s_val, acc0,acc1, tid,wt,zs);
  process_path<0,1,1>( 3, ch0, ws, x1s,x2s, wss,Ts,s_cnt,s_ij,s_val, acc0,acc1, tid,wt,zs);
  process_path<1,0,1>( 4, ch0, ws, x1s,x2s, wss,Ts,s_cnt,s_ij,s_val, acc0,acc1, tid,wt,zs);
  process_path<1,2,1>( 5, ch0, ws, x1s,x2s, wss,Ts,s_cnt,s_ij,s_val, acc0,acc1, tid,wt,zs);
  process_path<2,1,1>( 6, ch0, ws, x1s,x2s, wss,Ts,s_cnt,s_ij,s_val, acc0,acc1, tid,wt,zs);
  process_path<0,2,2>( 7, ch0, ws, x1s,x2s, wss,Ts,s_cnt,s_ij,s_val, acc0,acc1, tid,wt,zs);
  process_path<1,1,2>( 8, ch0, ws, x1s,x2s, wss,Ts,s_cnt,s_ij,s_val, acc0,acc1, tid,wt,zs);
  process_path<2,0,2>( 9, ch0, ws, x1s,x2s, wss,Ts,s_cnt,s_ij,s_val, acc0,acc1, tid,wt,zs);
  process_path<2,2,2>(10, ch0, ws, x1s,x2s, wss,Ts,s_cnt,s_ij,s_val, acc0,acc1, tid,wt,zs);

  const float A0 = 0.01804219591217583f;   // sqrt(1/3072)
  const float A1 = 0.02706329386826371f;   // sqrt(3)/64
  const float A2 = 0.03493856214843422f;   // sqrt(5)/64

  float* o = g_part[half] + (size_t)(zbase + zs) * DIMF;
  int w0 = wt, w1 = wt + 16;
  o[w0] = A0 * acc0[0];
  o[w1] = A0 * acc1[0];
  #pragma unroll
  for (int k = 0; k < 3; ++k){
    o[32 + w0*3 + k] = A1 * acc0[1+k];
    o[32 + w1*3 + k] = A1 * acc1[1+k];
  }
  #pragma unroll
  for (int k = 0; k < 5; ++k){
    o[128 + w0*5 + k] = A2 * acc0[4+k];
    o[128 + w1*5 + k] = A2 * acc1[4+k];
  }
}

__global__ void reduce_kernel(float* __restrict__ out){
  int i = blockIdx.x * blockDim.x + threadIdx.x;   // float4 index
  float4 a = ((const float4*)g_part[0])[i];
  float4 b = ((const float4*)g_part[1])[i];
  float4 c = ((const float4*)g_part[2])[i];
  float4 d = ((const float4*)g_part[3])[i];
  float4 r;
  r.x = (a.x + b.x) + (c.x + d.x);
  r.y = (a.y + b.y) + (c.y + d.y);
  r.z = (a.z + b.z) + (c.z + d.z);
  r.w = (a.w + b.w) + (c.w + d.w);
  ((float4*)out)[i] = r;
}

extern "C" void kernel_launch(void* const* d_in, const int* in_sizes, int n_in,
                              void* d_out, int out_size) {
  const float* x1 = (const float*)d_in[0];
  const float* x2 = (const float*)d_in[1];
  const float* ws = (const float*)d_in[2];
  float* out = (float*)d_out;
  (void)in_sizes; (void)n_in; (void)out_size;
  w3j_init<<<NPATH, 128>>>();
  tp_kernel<<<(2048/BZ)*UVS, NT>>>(x1, x2, ws);
  reduce_kernel<<<(2048*DIMF/4)/256, 256>>>(out);
}

// round 5
// speedup vs baseline: 1.6153x; 1.1444x over previous
#include <cuda_runtime.h>
#include <math.h>
#include <string.h>

#define NPATH 11
#define DIMF  288
#define BZ    8
#define CHK   64
#define NT    128
#define UVS   8            // uv-split factor
#define CHPC  (16/UVS)     // chunks per CTA per path
#define WPAD  68           // padded stride for transposed weights
#define X1S   289
#define X2S   288

static const int hc_l1[NPATH] = {0,1,2,0,1,1,2,0,1,2,2};
static const int hc_l2[NPATH] = {0,1,2,1,0,2,1,2,1,0,2};
static const int hc_lo[NPATH] = {0,0,0,1,1,1,1,2,2,2,2};

__device__ int   g_cnt [NPATH][5];
__device__ int   g_ije [NPATH][5][32];
__device__ float g_vale[NPATH][5][32];
__device__ float g_part[UVS][2048*DIMF];

// ---------------- host-side Wigner-3j (exact port of reference) ------------
static double hfact(int n){ double r=1.0; for(int i=2;i<=n;++i) r*=i; return r; }

static double h_su2(int j1,int m1,int j2,int m2,int j3,int m3){
  if (m1+m2 != m3) return 0.0;
  int vmin = -j1+j2+m3; if (-j1+m1 > vmin) vmin = -j1+m1; if (vmin < 0) vmin = 0;
  int vmax = j2+j3+m1; if (j3-j1+j2 < vmax) vmax = j3-j1+j2; if (j3+m3 < vmax) vmax = j3+m3;
  if (vmax < vmin) return 0.0;
  double C = sqrt((2.0*j3+1.0)
    * hfact(j3+j1-j2)*hfact(j3-j1+j2)*hfact(j1+j2-j3)*hfact(j3+m3)*hfact(j3-m3)
    / (hfact(j1+j2+j3+1)*hfact(j1-m1)*hfact(j1+m1)*hfact(j2-m2)*hfact(j2+m2)));
  double S = 0.0;
  for (int v = vmin; v <= vmax; ++v){
    double t = hfact(j2+j3+m1-v)*hfact(j1-m1+v)
             / (hfact(v)*hfact(j3-j1+j2-v)*hfact(j3+m3-v)*hfact(v+j1-j2-m3));
    S += ((v+j2+m2)&1) ? -t : t;
  }
  return C*S;
}

static void h_q(int l,int a,int b,double&re,double&im){
  double r=0.0,i=0.0; int m=a-l; const double s2=0.70710678118654752440;
  if (m<0){ if (b==l-m) r=s2; if (b==l+m) i=-s2; }
  else if (m==0){ if (b==l) r=1.0; }
  else { double s=(m&1)?-1.0:1.0; if (b==l+m) r=s*s2; if (b==l-m) i=s*s2; }
  if (l==1){ double t=r; r=i; i=-t; }       // *(-i)
  else if (l==2){ r=-r; i=-i; }             // *(-1)
  re=r; im=i;
}

static void compute_w3j(int cnt[NPATH][5], int ije[NPATH][5][32], float vale[NPATH][5][32]){
  for (int p=0;p<NPATH;++p){
    int l1=hc_l1[p], l2=hc_l2[p], l3=hc_lo[p];
    int d1=2*l1+1, d2=2*l2+1, d3=2*l3+1;
    double cg[125]; for (int e=0;e<125;++e) cg[e]=0.0;
    for (int i=0;i<d1;++i) for (int k=0;k<d2;++k){
      int m1=i-l1, m2=k-l2;
      if (m1+m2 >= -l3 && m1+m2 <= l3)
        cg[(i*d2+k)*d3 + (l3+m1+m2)] = h_su2(l1,m1,l2,m2,l3,m1+m2);
    }
    double Cv[125]; double nrm=0.0;
    for (int jj=0;jj<d1;++jj) for (int ll=0;ll<d2;++ll) for (int mm=0;mm<d3;++mm){
      double cr=0.0;
      for (int i=0;i<d1;++i){
        double q1r,q1i; h_q(l1,i,jj,q1r,q1i);
        if (q1r==0.0 && q1i==0.0) continue;
        for (int k=0;k<d2;++k){
          double q2r,q2i; h_q(l2,k,ll,q2r,q2i);
          if (q2r==0.0 && q2i==0.0) continue;
          int n=(i-l1)+(k-l2)+l3;
          if (n<0 || n>=d3) continue;
          double g=cg[(i*d2+k)*d3+n];
          if (g==0.0) continue;
          double q3r,q3i; h_q(l3,n,mm,q3r,q3i); q3i=-q3i;
          double ar=q1r*q2r-q1i*q2i, ai=q1r*q2i+q1i*q2r;
          cr += g*(ar*q3r - ai*q3i);
        }
      }
      Cv[(jj*d2+ll)*d3+mm]=cr; nrm += cr*cr;
    }
    double inorm = 1.0/sqrt(nrm);
    for (int mm=0;mm<d3;++mm){
      int c=0;
      for (int i=0;i<d1;++i) for (int j=0;j<d2;++j){
        double v = Cv[(i*d2+j)*d3+mm]*inorm;
        if (fabs(v) > 1e-9){
          ije [p][mm][c] = i | ((j*32)<<16);   // a1 offset | a2t offset
          vale[p][mm][c] = (float)v;
          ++c;
        }
      }
      cnt[p][mm] = (c+3)&~3;                   // padded entries are zeros
    }
  }
}

// ------------------------- main kernel -------------------------------------
template<int L1, int L2, int LO>
__device__ __forceinline__ void process_path(
    int p, int ch0, const float* __restrict__ ws,
    const float* x1s, const float* x2t,
    float* wss, float* Ts, int* s_cnt, int* s_ij, float* s_val,
    float* acc0, float* acc1, int tid, int wt, int zs)
{
  constexpr int D1 = 2*L1+1, K = 2*LO+1;
  constexpr int O1  = (L1==0)?0:((L1==1)?32:128);
  constexpr int O2T = (L2==0)?0:((L2==1)?32:128);
  constexpr int AO  = (LO==0)?0:((LO==1)?1:4);

  __syncthreads();
  if (tid < K) s_cnt[tid] = g_cnt[p][tid];
  for (int e = tid; e < K*32; e += NT){
    s_ij [e] = g_ije [p][e>>5][e&31];
    s_val[e] = g_vale[p][e>>5][e&31];
  }
  const float* wsp = ws + (size_t)p * 32768;

  for (int ch = ch0; ch < ch0 + CHPC; ++ch){
    __syncthreads();
    for (int e = tid; e < CHK*32; e += NT){
      int c = e >> 5, w = e & 31;
      wss[w*WPAD + c] = __ldg(wsp + ch*CHK*32 + e);
    }
    // build T[z][k][c]: a1 broadcast, a2 conflict-free (v contiguous)
    for (int e = tid; e < CHK*BZ; e += NT){
      int c = e & (CHK-1);
      int z = e >> 6;
      int uv = ch*CHK + c;
      const float* a1 = x1s + z*X1S + O1 + (uv>>5)*D1;
      const float* a2 = x2t + z*X2S + O2T + (uv&31);
      #pragma unroll
      for (int k = 0; k < K; ++k){
        int cnt4 = s_cnt[k] >> 2;
        const int4*   ij4 = (const int4*)  (s_ij  + (k<<5));
        const float4* vl4 = (const float4*)(s_val + (k<<5));
        float t0=0.f, t1=0.f, t2=0.f, t3=0.f;
        for (int q = 0; q < cnt4; ++q){
          int4 ij = ij4[q]; float4 vl = vl4[q];
          t0 = fmaf(vl.x, a1[ij.x & 0xffff] * a2[ij.x >> 16], t0);
          t1 = fmaf(vl.y, a1[ij.y & 0xffff] * a2[ij.y >> 16], t1);
          t2 = fmaf(vl.z, a1[ij.z & 0xffff] * a2[ij.z >> 16], t2);
          t3 = fmaf(vl.w, a1[ij.w & 0xffff] * a2[ij.w >> 16], t3);
        }
        Ts[(z*K + k)*CHK + c] = (t0 + t1) + (t2 + t3);
      }
    }
    __syncthreads();
    const float4* wv0 = (const float4*)(wss + wt*WPAD);
    const float4* wv1 = (const float4*)(wss + (wt+16)*WPAD);
    #pragma unroll 4
    for (int c4 = 0; c4 < CHK/4; ++c4){
      float4 wa = wv0[c4];
      float4 wb = wv1[c4];
      #pragma unroll
      for (int k = 0; k < K; ++k){
        float4 t = ((const float4*)(Ts + (zs*K + k)*CHK))[c4];
        acc0[AO+k] = fmaf(wa.x, t.x, fmaf(wa.y, t.y, fmaf(wa.z, t.z, fmaf(wa.w, t.w, acc0[AO+k]))));
        acc1[AO+k] = fmaf(wb.x, t.x, fmaf(wb.y, t.y, fmaf(wb.z, t.z, fmaf(wb.w, t.w, acc1[AO+k]))));
      }
    }
  }
}

__global__ void __launch_bounds__(NT, 5) tp_kernel(
    const float* __restrict__ x1, const float* __restrict__ x2,
    const float* __restrict__ ws)
{
  __shared__ float x1s[BZ*X1S];
  __shared__ float x2t[BZ*X2S];
  __shared__ float wss[32*WPAD];
  __shared__ float Ts [BZ*5*CHK];
  __shared__ float s_val[5*32];
  __shared__ int   s_ij [5*32];
  __shared__ int   s_cnt[5];

  int tid  = threadIdx.x;
  int wt   = tid & 15;
  int zs   = tid >> 4;
  int bid  = blockIdx.x;
  int half = bid & (UVS-1);
  int ch0  = half * CHPC;
  int zbase = (bid >> 3) * BZ;

  for (int e = tid; e < BZ*DIMF; e += NT){
    int z = e / DIMF, c = e - z*DIMF;
    x1s[z*X1S + c] = x1[(size_t)(zbase+z)*DIMF + c];
    float v2 = x2[(size_t)(zbase+z)*DIMF + c];
    int dst;
    if (c < 32) dst = c;
    else if (c < 128){ int idx = c - 32;  dst = 32  + (idx % 3)*32 + idx/3; }
    else             { int idx = c - 128; dst = 128 + (idx % 5)*32 + idx/5; }
    x2t[z*X2S + dst] = v2;
  }

  float acc0[9], acc1[9];
  #pragma unroll
  for (int i = 0; i < 9; ++i){ acc0[i]=0.f; acc1[i]=0.f; }

  process_path<0,0,0>( 0, ch0, ws, x1s,x2t, wss,Ts,s_cnt,s_ij,s_val, acc0,acc1, tid,wt,zs);
  process_path<1,1,0>( 1, ch0, ws, x1s,x2t, wss,Ts,s_cnt,s_ij,s_val, acc0,acc1, tid,wt,zs);
  process_path<2,2,0>( 2, ch0, ws, x1s,x2t, wss,Ts,s_cnt,s_ij,s_val, acc0,acc1, tid,wt,zs);
  process_path<0,1,1>( 3, ch0, ws, x1s,x2t, wss,Ts,s_cnt,s_ij,s_val, acc0,acc1, tid,wt,zs);
  process_path<1,0,1>( 4, ch0, ws, x1s,x2t, wss,Ts,s_cnt,s_ij,s_val, acc0,acc1, tid,wt,zs);
  process_path<1,2,1>( 5, ch0, ws, x1s,x2t, wss,Ts,s_cnt,s_ij,s_val, acc0,acc1, tid,wt,zs);
  process_path<2,1,1>( 6, ch0, ws, x1s,x2t, wss,Ts,s_cnt,s_ij,s_val, acc0,acc1, tid,wt,zs);
  process_path<0,2,2>( 7, ch0, ws, x1s,x2t, wss,Ts,s_cnt,s_ij,s_val, acc0,acc1, tid,wt,zs);
  process_path<1,1,2>( 8, ch0, ws, x1s,x2t, wss,Ts,s_cnt,s_ij,s_val, acc0,acc1, tid,wt,zs);
  process_path<2,0,2>( 9, ch0, ws, x1s,x2t, wss,Ts,s_cnt,s_ij,s_val, acc0,acc1, tid,wt,zs);
  process_path<2,2,2>(10, ch0, ws, x1s,x2t, wss,Ts,s_cnt,s_ij,s_val, acc0,acc1, tid,wt,zs);

  const float A0 = 0.01804219591217583f;   // sqrt(1/3072)
  const float A1 = 0.02706329386826371f;   // sqrt(3)/64
  const float A2 = 0.03493856214843422f;   // sqrt(5)/64

  float* o = g_part[half] + (size_t)(zbase + zs) * DIMF;
  int w0 = wt, w1 = wt + 16;
  o[w0] = A0 * acc0[0];
  o[w1] = A0 * acc1[0];
  #pragma unroll
  for (int k = 0; k < 3; ++k){
    o[32 + w0*3 + k] = A1 * acc0[1+k];
    o[32 + w1*3 + k] = A1 * acc1[1+k];
  }
  #pragma unroll
  for (int k = 0; k < 5; ++k){
    o[128 + w0*5 + k] = A2 * acc0[4+k];
    o[128 + w1*5 + k] = A2 * acc1[4+k];
  }
}

__global__ void reduce_kernel(float* __restrict__ out){
  int i = blockIdx.x * blockDim.x + threadIdx.x;
  float4 r = make_float4(0.f, 0.f, 0.f, 0.f);
  #pragma unroll
  for (int s = 0; s < UVS; ++s){
    float4 a = ((const float4*)g_part[s])[i];
    r.x += a.x; r.y += a.y; r.z += a.z; r.w += a.w;
  }
  ((float4*)out)[i] = r;
}

extern "C" void kernel_launch(void* const* d_in, const int* in_sizes, int n_in,
                              void* d_out, int out_size) {
  const float* x1 = (const float*)d_in[0];
  const float* x2 = (const float*)d_in[1];
  const float* ws = (const float*)d_in[2];
  float* out = (float*)d_out;
  (void)in_sizes; (void)n_in; (void)out_size;

  static int   h_cnt [NPATH][5];
  static int   h_ije [NPATH][5][32];
  static float h_vale[NPATH][5][32];
  memset(h_cnt, 0, sizeof(h_cnt));
  memset(h_ije, 0, sizeof(h_ije));
  memset(h_vale, 0, sizeof(h_vale));
  compute_w3j(h_cnt, h_ije, h_vale);

  cudaMemcpyToSymbolAsync(g_cnt,  h_cnt,  sizeof(h_cnt),  0, cudaMemcpyHostToDevice, 0);
  cudaMemcpyToSymbolAsync(g_ije,  h_ije,  sizeof(h_ije),  0, cudaMemcpyHostToDevice, 0);
  cudaMemcpyToSymbolAsync(g_vale, h_vale, sizeof(h_vale), 0, cudaMemcpyHostToDevice, 0);

  tp_kernel<<<(2048/BZ)*UVS, NT>>>(x1, x2, ws);
  reduce_kernel<<<(2048*DIMF/4)/256, 256>>>(out);
}

// round 6
// speedup vs baseline: 2.6018x; 1.6107x over previous
#include <cuda_runtime.h>
#include <math.h>
#include <string.h>

#define NPATH 11
#define DIMF  288
#define BZ    8
#define CHK   64
#define NT    128
#define UVS   8            // uv-split factor
#define CHPC  (16/UVS)     // chunks per CTA per path
#define WPAD  68           // padded stride for transposed weights
#define X1S   289
#define X2S   288

static const int hc_l1[NPATH] = {0,1,2,0,1,1,2,0,1,2,2};
static const int hc_l2[NPATH] = {0,1,2,1,0,2,1,2,1,0,2};
static const int hc_lo[NPATH] = {0,0,0,1,1,1,1,2,2,2,2};

__device__ float g_C[NPATH][125];          // dense normalized w3j, [(i*D2+j)*K + k]
__device__ float g_part[UVS][2048*DIMF];   // scratch partials

// ---------------- host-side Wigner-3j (exact port of reference) ------------
static double hfact(int n){ double r=1.0; for(int i=2;i<=n;++i) r*=i; return r; }

static double h_su2(int j1,int m1,int j2,int m2,int j3,int m3){
  if (m1+m2 != m3) return 0.0;
  int vmin = -j1+j2+m3; if (-j1+m1 > vmin) vmin = -j1+m1; if (vmin < 0) vmin = 0;
  int vmax = j2+j3+m1; if (j3-j1+j2 < vmax) vmax = j3-j1+j2; if (j3+m3 < vmax) vmax = j3+m3;
  if (vmax < vmin) return 0.0;
  double C = sqrt((2.0*j3+1.0)
    * hfact(j3+j1-j2)*hfact(j3-j1+j2)*hfact(j1+j2-j3)*hfact(j3+m3)*hfact(j3-m3)
    / (hfact(j1+j2+j3+1)*hfact(j1-m1)*hfact(j1+m1)*hfact(j2-m2)*hfact(j2+m2)));
  double S = 0.0;
  for (int v = vmin; v <= vmax; ++v){
    double t = hfact(j2+j3+m1-v)*hfact(j1-m1+v)
             / (hfact(v)*hfact(j3-j1+j2-v)*hfact(j3+m3-v)*hfact(v+j1-j2-m3));
    S += ((v+j2+m2)&1) ? -t : t;
  }
  return C*S;
}

static void h_q(int l,int a,int b,double&re,double&im){
  double r=0.0,i=0.0; int m=a-l; const double s2=0.70710678118654752440;
  if (m<0){ if (b==l-m) r=s2; if (b==l+m) i=-s2; }
  else if (m==0){ if (b==l) r=1.0; }
  else { double s=(m&1)?-1.0:1.0; if (b==l+m) r=s*s2; if (b==l-m) i=s*s2; }
  if (l==1){ double t=r; r=i; i=-t; }       // *(-i)
  else if (l==2){ r=-r; i=-i; }             // *(-1)
  re=r; im=i;
}

static void compute_w3j_dense(float Cd[NPATH][125]){
  for (int p=0;p<NPATH;++p){
    int l1=hc_l1[p], l2=hc_l2[p], l3=hc_lo[p];
    int d1=2*l1+1, d2=2*l2+1, d3=2*l3+1;
    double cg[125]; for (int e=0;e<125;++e) cg[e]=0.0;
    for (int i=0;i<d1;++i) for (int k=0;k<d2;++k){
      int m1=i-l1, m2=k-l2;
      if (m1+m2 >= -l3 && m1+m2 <= l3)
        cg[(i*d2+k)*d3 + (l3+m1+m2)] = h_su2(l1,m1,l2,m2,l3,m1+m2);
    }
    double Cv[125]; double nrm=0.0;
    for (int jj=0;jj<d1;++jj) for (int ll=0;ll<d2;++ll) for (int mm=0;mm<d3;++mm){
      double cr=0.0;
      for (int i=0;i<d1;++i){
        double q1r,q1i; h_q(l1,i,jj,q1r,q1i);
        if (q1r==0.0 && q1i==0.0) continue;
        for (int k=0;k<d2;++k){
          double q2r,q2i; h_q(l2,k,ll,q2r,q2i);
          if (q2r==0.0 && q2i==0.0) continue;
          int n=(i-l1)+(k-l2)+l3;
          if (n<0 || n>=d3) continue;
          double g=cg[(i*d2+k)*d3+n];
          if (g==0.0) continue;
          double q3r,q3i; h_q(l3,n,mm,q3r,q3i); q3i=-q3i;
          double ar=q1r*q2r-q1i*q2i, ai=q1r*q2i+q1i*q2r;
          cr += g*(ar*q3r - ai*q3i);
        }
      }
      Cv[(jj*d2+ll)*d3+mm]=cr; nrm += cr*cr;
    }
    double inorm = 1.0/sqrt(nrm);
    for (int e=0;e<125;++e) Cd[p][e]=0.f;
    for (int e=0;e<d1*d2*d3;++e) Cd[p][e] = (float)(Cv[e]*inorm);
  }
}

// ------------------------- main kernel -------------------------------------
template<int L1, int L2, int LO>
__device__ __forceinline__ void process_path(
    int p, int ch0, const float* __restrict__ ws,
    const float* x1s, const float* x2t,
    float* wss, float* Ts, float* sC,
    float* acc0, float* acc1, int tid, int wt, int zs)
{
  constexpr int D1 = 2*L1+1, D2 = 2*L2+1, K = 2*LO+1;
  constexpr int O1  = (L1==0)?0:((L1==1)?32:128);
  constexpr int O2T = (L2==0)?0:((L2==1)?32:128);
  constexpr int AO  = (LO==0)?0:((LO==1)?1:4);

  for (int e = tid; e < K*D1*D2; e += NT) sC[e] = g_C[p][e];
  const float* wsp = ws + (size_t)p * 32768;

  for (int ch = ch0; ch < ch0 + CHPC; ++ch){
    __syncthreads();
    // prefetch weights into registers (hide L2 latency under T-build)
    float wreg[16];
    #pragma unroll
    for (int r = 0; r < 16; ++r)
      wreg[r] = __ldg(wsp + ch*2048 + r*128 + tid);

    // dense unrolled T-build: thread owns (c, z-base), 2 z per pass, 2 passes
    {
      int c  = tid & 63;
      int zb = tid >> 6;            // 0 or 1
      int uv = ch*CHK + c;
      int u  = uv >> 5, v = uv & 31;
      #pragma unroll
      for (int rp = 0; rp < 2; ++rp){
        int za = zb + rp*4;
        int zc = za + 2;
        float A0[D1], A1[D1], B0[D2], B1[D2];
        #pragma unroll
        for (int i = 0; i < D1; ++i){
          A0[i] = x1s[za*X1S + O1 + u*D1 + i];
          A1[i] = x1s[zc*X1S + O1 + u*D1 + i];
        }
        #pragma unroll
        for (int j = 0; j < D2; ++j){
          B0[j] = x2t[za*X2S + O2T + j*32 + v];
          B1[j] = x2t[zc*X2S + O2T + j*32 + v];
        }
        float t0[K], t1[K];
        #pragma unroll
        for (int k = 0; k < K; ++k){ t0[k]=0.f; t1[k]=0.f; }
        #pragma unroll
        for (int i = 0; i < D1; ++i){
          #pragma unroll
          for (int j = 0; j < D2; ++j){
            float p0 = A0[i]*B0[j];
            float p1 = A1[i]*B1[j];
            #pragma unroll
            for (int k = 0; k < K; ++k){
              float cf = sC[(i*D2+j)*K + k];
              t0[k] = fmaf(cf, p0, t0[k]);
              t1[k] = fmaf(cf, p1, t1[k]);
            }
          }
        }
        #pragma unroll
        for (int k = 0; k < K; ++k){
          Ts[(za*K + k)*CHK + c] = t0[k];
          Ts[(zc*K + k)*CHK + c] = t1[k];
        }
      }
    }
    // store weights transposed: wss[w*WPAD + c]
    #pragma unroll
    for (int r = 0; r < 16; ++r){
      int e = r*128 + tid;
      wss[(e & 31)*WPAD + (e >> 5)] = wreg[r];
    }
    __syncthreads();
    // vectorized rank-1 sweep: float4 over c
    const float4* wv0 = (const float4*)(wss + wt*WPAD);
    const float4* wv1 = (const float4*)(wss + (wt+16)*WPAD);
    #pragma unroll 4
    for (int c4 = 0; c4 < CHK/4; ++c4){
      float4 wa = wv0[c4];
      float4 wb = wv1[c4];
      #pragma unroll
      for (int k = 0; k < K; ++k){
        float4 t = ((const float4*)(Ts + (zs*K + k)*CHK))[c4];
        acc0[AO+k] = fmaf(wa.x, t.x, fmaf(wa.y, t.y, fmaf(wa.z, t.z, fmaf(wa.w, t.w, acc0[AO+k]))));
        acc1[AO+k] = fmaf(wb.x, t.x, fmaf(wb.y, t.y, fmaf(wb.z, t.z, fmaf(wb.w, t.w, acc1[AO+k]))));
      }
    }
  }
}

__global__ void __launch_bounds__(NT, 5) tp_kernel(
    const float* __restrict__ x1, const float* __restrict__ x2,
    const float* __restrict__ ws)
{
  __shared__ float x1s[BZ*X1S];
  __shared__ float x2t[BZ*X2S];
  __shared__ float wss[32*WPAD];
  __shared__ float Ts [BZ*5*CHK];
  __shared__ float sC [125];

  int tid  = threadIdx.x;
  int wt   = tid & 15;
  int zs   = tid >> 4;
  int bid  = blockIdx.x;
  int half = bid & (UVS-1);
  int ch0  = half * CHPC;
  int zbase = (bid >> 3) * BZ;

  for (int e = tid; e < BZ*DIMF; e += NT){
    int z = e / DIMF, c = e - z*DIMF;
    x1s[z*X1S + c] = x1[(size_t)(zbase+z)*DIMF + c];
    float v2 = x2[(size_t)(zbase+z)*DIMF + c];
    int dst;
    if (c < 32) dst = c;
    else if (c < 128){ int idx = c - 32;  dst = 32  + (idx % 3)*32 + idx/3; }
    else             { int idx = c - 128; dst = 128 + (idx % 5)*32 + idx/5; }
    x2t[z*X2S + dst] = v2;
  }

  float acc0[9], acc1[9];
  #pragma unroll
  for (int i = 0; i < 9; ++i){ acc0[i]=0.f; acc1[i]=0.f; }

  process_path<0,0,0>( 0, ch0, ws, x1s,x2t, wss,Ts,sC, acc0,acc1, tid,wt,zs);
  process_path<1,1,0>( 1, ch0, ws, x1s,x2t, wss,Ts,sC, acc0,acc1, tid,wt,zs);
  process_path<2,2,0>( 2, ch0, ws, x1s,x2t, wss,Ts,sC, acc0,acc1, tid,wt,zs);
  process_path<0,1,1>( 3, ch0, ws, x1s,x2t, wss,Ts,sC, acc0,acc1, tid,wt,zs);
  process_path<1,0,1>( 4, ch0, ws, x1s,x2t, wss,Ts,sC, acc0,acc1, tid,wt,zs);
  process_path<1,2,1>( 5, ch0, ws, x1s,x2t, wss,Ts,sC, acc0,acc1, tid,wt,zs);
  process_path<2,1,1>( 6, ch0, ws, x1s,x2t, wss,Ts,sC, acc0,acc1, tid,wt,zs);
  process_path<0,2,2>( 7, ch0, ws, x1s,x2t, wss,Ts,sC, acc0,acc1, tid,wt,zs);
  process_path<1,1,2>( 8, ch0, ws, x1s,x2t, wss,Ts,sC, acc0,acc1, tid,wt,zs);
  process_path<2,0,2>( 9, ch0, ws, x1s,x2t, wss,Ts,sC, acc0,acc1, tid,wt,zs);
  process_path<2,2,2>(10, ch0, ws, x1s,x2t, wss,Ts,sC, acc0,acc1, tid,wt,zs);

  const float A0 = 0.01804219591217583f;   // sqrt(1/3072)
  const float A1 = 0.02706329386826371f;   // sqrt(3)/64
  const float A2 = 0.03493856214843422f;   // sqrt(5)/64

  float* o = g_part[half] + (size_t)(zbase + zs) * DIMF;
  int w0 = wt, w1 = wt + 16;
  o[w0] = A0 * acc0[0];
  o[w1] = A0 * acc1[0];
  #pragma unroll
  for (int k = 0; k < 3; ++k){
    o[32 + w0*3 + k] = A1 * acc0[1+k];
    o[32 + w1*3 + k] = A1 * acc1[1+k];
  }
  #pragma unroll
  for (int k = 0; k < 5; ++k){
    o[128 + w0*5 + k] = A2 * acc0[4+k];
    o[128 + w1*5 + k] = A2 * acc1[4+k];
  }
}

__global__ void reduce_kernel(float* __restrict__ out){
  int i = blockIdx.x * blockDim.x + threadIdx.x;
  float4 r = make_float4(0.f, 0.f, 0.f, 0.f);
  #pragma unroll
  for (int s = 0; s < UVS; ++s){
    float4 a = ((const float4*)g_part[s])[i];
    r.x += a.x; r.y += a.y; r.z += a.z; r.w += a.w;
  }
  ((float4*)out)[i] = r;
}

extern "C" void kernel_launch(void* const* d_in, const int* in_sizes, int n_in,
                              void* d_out, int out_size) {
  const float* x1 = (const float*)d_in[0];
  const float* x2 = (const float*)d_in[1];
  const float* ws = (const float*)d_in[2];
  float* out = (float*)d_out;
  (void)in_sizes; (void)n_in; (void)out_size;

  static float h_C[NPATH][125];
  compute_w3j_dense(h_C);
  cudaMemcpyToSymbolAsync(g_C, h_C, sizeof(h_C), 0, cudaMemcpyHostToDevice, 0);

  tp_kernel<<<(2048/BZ)*UVS, NT>>>(x1, x2, ws);
  reduce_kernel<<<(2048*DIMF/4)/256, 256>>>(out);
}